// round 12
// baseline (speedup 1.0000x reference)
#include <cuda_runtime.h>

#define L_CHK 32                     // chunk length along T
#define BATCH 8                      // load batch for MLP
#define MAX_CPL 16                   // max chunks per lane in warp-scan pass2
#define SCRATCH_CAP_V4 (1 << 20)     // float4 count -> 16 MB each

// Scratch, pair-packed: float4 [c][q] = (re0,im0,re1,im1) for channels 2q,2q+1.
// float2 view at [c*D + d] is layout-identical (d = 2q + half).
__device__ float4 g_carry4 [SCRATCH_CAP_V4];
__device__ float4 g_prefix4[SCRATCH_CAP_V4];

// ===========================================================================
// Pass 1 (vector, D even): 2 channels/thread, float2 x loads, batched x8.
// ===========================================================================
__global__ void __launch_bounds__(256) dln_pass1_v2(
    const float* __restrict__ x, const float* __restrict__ sz,
    const float* __restrict__ th, int D, int T, int C)
{
    const int P2 = D >> 1;
    const int q  = blockIdx.x * blockDim.x + threadIdx.x;
    const int c  = blockIdx.y;
    if (q >= P2 || c >= C) return;

    const int t0  = c * L_CHK;
    const int len = (T - t0 < L_CHK) ? (T - t0) : L_CHK;

    const float2 s2 = ((const float2*)sz)[q];
    const float2 t2 = ((const float2*)th)[q];
    const float r0 = expf(-expf(s2.x)), r1 = expf(-expf(s2.y));
    float si0, co0, si1, co1;
    sincosf(t2.x, &si0, &co0);
    sincosf(t2.y, &si1, &co1);
    const float zr0 = r0 * co0, zi0 = r0 * si0;
    const float zr1 = r1 * co1, zi1 = r1 * si1;

    const float2* xp = (const float2*)(x + (long long)t0 * D) + q;

    float vr0 = 0.f, vi0 = 0.f, vr1 = 0.f, vi1 = 0.f;
    if (len == L_CHK) {
#pragma unroll
        for (int tb = 0; tb < L_CHK; tb += BATCH) {
            float2 xb[BATCH];
#pragma unroll
            for (int i = 0; i < BATCH; ++i)          // 8 LDG.64 in flight
                xb[i] = xp[(tb + i) * P2];
#pragma unroll
            for (int i = 0; i < BATCH; ++i) {
                float nvr = fmaf(zr0, vr0, fmaf(-zi0, vi0, xb[i].x));
                float nvi = fmaf(zi0, vr0, zr0 * vi0);
                vr0 = nvr; vi0 = nvi;
                nvr = fmaf(zr1, vr1, fmaf(-zi1, vi1, xb[i].y));
                nvi = fmaf(zi1, vr1, zr1 * vi1);
                vr1 = nvr; vi1 = nvi;
            }
        }
    } else {
        for (int t = 0; t < len; ++t) {
            const float2 xv = xp[t * P2];
            float nvr = fmaf(zr0, vr0, fmaf(-zi0, vi0, xv.x));
            float nvi = fmaf(zi0, vr0, zr0 * vi0);
            vr0 = nvr; vi0 = nvi;
            nvr = fmaf(zr1, vr1, fmaf(-zi1, vi1, xv.y));
            nvi = fmaf(zi1, vr1, zr1 * vi1);
            vr1 = nvr; vi1 = nvi;
        }
    }
    g_carry4[(long long)c * P2 + q] = make_float4(vr0, vi0, vr1, vi1);
}

// ===========================================================================
// Pass 2 (warp-per-channel Kogge-Stone scan over chunk carries).
// ===========================================================================
__global__ void __launch_bounds__(256) dln_pass2_w(
    const float* __restrict__ sz, const float* __restrict__ th,
    int D, int C, int cpl)
{
    const float2* carry2  = (const float2*)g_carry4;
    float2*       prefix2 = (float2*)g_prefix4;

    const int gtid = blockIdx.x * blockDim.x + threadIdx.x;
    const int d    = gtid >> 5;          // warp = channel
    const int lane = gtid & 31;
    if (d >= D) return;

    const float rL = expf(-(float)L_CHK * expf(sz[d]));   // |z|^L
    float si, co;
    sincosf((float)L_CHK * th[d], &si, &co);
    const float zr = rL * co, zi = rL * si;               // z^L

    float cr[MAX_CPL], ci[MAX_CPL];
#pragma unroll
    for (int i = 0; i < MAX_CPL; ++i) {
        if (i < cpl) {
            const int c = lane * cpl + i;
            if (c < C) {
                const float2 cv = carry2[(long long)c * D + d];
                cr[i] = cv.x; ci[i] = cv.y;
            } else { cr[i] = 0.f; ci[i] = 0.f; }
        }
    }

    float Pr = 1.f, Pi = 0.f, Vr = 0.f, Vi = 0.f;
#pragma unroll
    for (int i = 0; i < MAX_CPL; ++i) {
        if (i < cpl && lane * cpl + i < C) {
            const float nVr = fmaf(Vr, zr, fmaf(-Vi, zi, cr[i]));
            const float nVi = fmaf(Vr, zi, fmaf(Vi, zr, ci[i]));
            const float nPr = Pr * zr - Pi * zi;
            const float nPi = Pr * zi + Pi * zr;
            Vr = nVr; Vi = nVi; Pr = nPr; Pi = nPi;
        }
    }

#pragma unroll
    for (int k = 1; k < 32; k <<= 1) {
        const float aPr = __shfl_up_sync(0xffffffffu, Pr, k);
        const float aPi = __shfl_up_sync(0xffffffffu, Pi, k);
        const float aVr = __shfl_up_sync(0xffffffffu, Vr, k);
        const float aVi = __shfl_up_sync(0xffffffffu, Vi, k);
        if (lane >= k) {
            const float tVr = fmaf(aVr, Pr, fmaf(-aVi, Pi, Vr));
            const float tVi = fmaf(aVr, Pi, fmaf(aVi, Pr, Vi));
            const float tPr = aPr * Pr - aPi * Pi;
            const float tPi = aPr * Pi + aPi * Pr;
            Vr = tVr; Vi = tVi; Pr = tPr; Pi = tPi;
        }
    }

    float Rr = __shfl_up_sync(0xffffffffu, Vr, 1);
    float Ri = __shfl_up_sync(0xffffffffu, Vi, 1);
    if (lane == 0) { Rr = 0.f; Ri = 0.f; }

#pragma unroll
    for (int i = 0; i < MAX_CPL; ++i) {
        if (i < cpl) {
            const int c = lane * cpl + i;
            if (c < C) {
                prefix2[(long long)c * D + d] = make_float2(Rr, Ri);
                const float nRr = fmaf(Rr, zr, fmaf(-Ri, zi, cr[i]));
                const float nRi = fmaf(Rr, zi, fmaf(Ri, zr, ci[i]));
                Rr = nRr; Ri = nRi;
            }
        }
    }
}

// ===========================================================================
// Pass 3 (vector, REAL output): batched loads x8, batched streaming stores.
// ===========================================================================
__global__ void __launch_bounds__(256) dln_pass3_real_v2(
    const float* __restrict__ x, const float* __restrict__ sz,
    const float* __restrict__ th, float* __restrict__ out,
    int D, int T, int C, long long out_cap_floats)
{
    const int P2 = D >> 1;
    const int q  = blockIdx.x * blockDim.x + threadIdx.x;
    const int c  = blockIdx.y;
    if (q >= P2 || c >= C) return;

    const int t0  = c * L_CHK;
    const int len = (T - t0 < L_CHK) ? (T - t0) : L_CHK;

    const float2 s2 = ((const float2*)sz)[q];
    const float2 t2 = ((const float2*)th)[q];
    const float r0 = expf(-expf(s2.x)), r1 = expf(-expf(s2.y));
    float si0, co0, si1, co1;
    sincosf(t2.x, &si0, &co0);
    sincosf(t2.y, &si1, &co1);
    const float zr0 = r0 * co0, zi0 = r0 * si0;
    const float zr1 = r1 * co1, zi1 = r1 * si1;

    const float4 v0 = g_prefix4[(long long)c * P2 + q];
    float vr0 = v0.x, vi0 = v0.y, vr1 = v0.z, vi1 = v0.w;

    const float2* xp = (const float2*)(x + (long long)t0 * D) + q;

    if (len == L_CHK && (long long)(t0 + L_CHK) * D <= out_cap_floats) {
        float2* op = (float2*)(out + (long long)t0 * D) + q;
#pragma unroll
        for (int tb = 0; tb < L_CHK; tb += BATCH) {
            float2 xb[BATCH];
#pragma unroll
            for (int i = 0; i < BATCH; ++i)          // 8 LDG.64 in flight
                xb[i] = xp[(tb + i) * P2];
            float2 ob[BATCH];
#pragma unroll
            for (int i = 0; i < BATCH; ++i) {
                float nvr = fmaf(zr0, vr0, fmaf(-zi0, vi0, xb[i].x));
                float nvi = fmaf(zi0, vr0, zr0 * vi0);
                vr0 = nvr; vi0 = nvi;
                nvr = fmaf(zr1, vr1, fmaf(-zi1, vi1, xb[i].y));
                nvi = fmaf(zi1, vr1, zr1 * vi1);
                vr1 = nvr; vi1 = nvi;
                ob[i] = make_float2(vr0, vr1);
            }
#pragma unroll
            for (int i = 0; i < BATCH; ++i)          // 8 STG.64 streaming
                __stcs(op + (tb + i) * P2, ob[i]);
        }
    } else {
        for (int t = 0; t < len; ++t) {
            const float2 xv = xp[t * P2];
            float nvr = fmaf(zr0, vr0, fmaf(-zi0, vi0, xv.x));
            float nvi = fmaf(zi0, vr0, zr0 * vi0);
            vr0 = nvr; vi0 = nvi;
            nvr = fmaf(zr1, vr1, fmaf(-zi1, vi1, xv.y));
            nvi = fmaf(zi1, vr1, zr1 * vi1);
            vr1 = nvr; vi1 = nvi;
            const long long row = (long long)(t0 + t) * D + 2 * q;
            if (row     < out_cap_floats) __stcs(out + row,     vr0);
            if (row + 1 < out_cap_floats) __stcs(out + row + 1, vr1);
        }
    }
}

// ===========================================================================
// Scalar fallbacks (any D / interleaved mode) — float2 scratch view [c*D+d].
// ===========================================================================
__global__ void __launch_bounds__(256) dln_pass1_s(
    const float* __restrict__ x, const float* __restrict__ sz,
    const float* __restrict__ th, int D, int T, int C)
{
    float2* carry = (float2*)g_carry4;
    const int d = blockIdx.x * blockDim.x + threadIdx.x;
    const int c = blockIdx.y;
    if (d >= D || c >= C) return;
    const int t0  = c * L_CHK;
    const int len = (T - t0 < L_CHK) ? (T - t0) : L_CHK;
    const float r = expf(-expf(sz[d]));
    float si, co; sincosf(th[d], &si, &co);
    const float zr = r * co, zi = r * si;
    const float* xp = x + (long long)t0 * D + d;
    float vr = 0.f, vi = 0.f;
    for (int t = 0; t < len; ++t) {
        const float xv = xp[(long long)t * D];
        const float nvr = fmaf(zr, vr, fmaf(-zi, vi, xv));
        const float nvi = fmaf(zi, vr, zr * vi);
        vr = nvr; vi = nvi;
    }
    carry[(long long)c * D + d] = make_float2(vr, vi);
}

__global__ void __launch_bounds__(256) dln_pass2_s(
    const float* __restrict__ sz, const float* __restrict__ th, int D, int C)
{
    float2* carry  = (float2*)g_carry4;
    float2* prefix = (float2*)g_prefix4;
    const int d = blockIdx.x * blockDim.x + threadIdx.x;
    if (d >= D) return;
    const float rL = expf(-(float)L_CHK * expf(sz[d]));
    float si, co; sincosf((float)L_CHK * th[d], &si, &co);
    const float zLr = rL * co, zLi = rL * si;
    float vr = 0.f, vi = 0.f;
    for (int c = 0; c < C; ++c) {
        const long long idx = (long long)c * D + d;
        prefix[idx] = make_float2(vr, vi);
        const float2 cv = carry[idx];
        const float nvr = fmaf(zLr, vr, fmaf(-zLi, vi, cv.x));
        const float nvi = fmaf(zLi, vr, fmaf(zLr, vi, cv.y));
        vr = nvr; vi = nvi;
    }
}

__global__ void __launch_bounds__(256) dln_pass3_real_s(
    const float* __restrict__ x, const float* __restrict__ sz,
    const float* __restrict__ th, float* __restrict__ out,
    int D, int T, int C, long long out_cap_floats)
{
    float2* prefix = (float2*)g_prefix4;
    const int d = blockIdx.x * blockDim.x + threadIdx.x;
    const int c = blockIdx.y;
    if (d >= D || c >= C) return;
    const int t0  = c * L_CHK;
    const int len = (T - t0 < L_CHK) ? (T - t0) : L_CHK;
    const float r = expf(-expf(sz[d]));
    float si, co; sincosf(th[d], &si, &co);
    const float zr = r * co, zi = r * si;
    const float2 v0 = prefix[(long long)c * D + d];
    float vr = v0.x, vi = v0.y;
    const float* xp = x + (long long)t0 * D + d;
    for (int t = 0; t < len; ++t) {
        const float xv = xp[(long long)t * D];
        const float nvr = fmaf(zr, vr, fmaf(-zi, vi, xv));
        const float nvi = fmaf(zi, vr, zr * vi);
        vr = nvr; vi = nvi;
        const long long lidx = (long long)(t0 + t) * D + d;
        if (lidx < out_cap_floats) __stcs(out + lidx, vr);
    }
}

__global__ void __launch_bounds__(256) dln_pass3_cplx_s(
    const float* __restrict__ x, const float* __restrict__ sz,
    const float* __restrict__ th, float* __restrict__ out,
    int D, int T, int C, long long out_cap_floats)
{
    float2* prefix = (float2*)g_prefix4;
    const int d = blockIdx.x * blockDim.x + threadIdx.x;
    const int c = blockIdx.y;
    if (d >= D || c >= C) return;
    const int t0  = c * L_CHK;
    const int len = (T - t0 < L_CHK) ? (T - t0) : L_CHK;
    const float r = expf(-expf(sz[d]));
    float si, co; sincosf(th[d], &si, &co);
    const float zr = r * co, zi = r * si;
    const float2 v0 = prefix[(long long)c * D + d];
    float vr = v0.x, vi = v0.y;
    const float* xp = x + (long long)t0 * D + d;
    for (int t = 0; t < len; ++t) {
        const float xv = xp[(long long)t * D];
        const float nvr = fmaf(zr, vr, fmaf(-zi, vi, xv));
        const float nvi = fmaf(zi, vr, zr * vi);
        vr = nvr; vi = nvi;
        const long long o = 2 * ((long long)(t0 + t) * D + d);
        if (o + 1 < out_cap_floats) { __stcs(out + o, vr); __stcs(out + o + 1, vi); }
    }
}

extern "C" void kernel_launch(void* const* d_in, const int* in_sizes, int n_in,
                              void* d_out, int out_size)
{
    if (n_in < 3) return;

    int xi = 0;
    for (int i = 1; i < n_in; ++i)
        if (in_sizes[i] > in_sizes[xi]) xi = i;

    const float* x = (const float*)d_in[xi];
    const float* sv[2] = {nullptr, nullptr};
    long long    ss[2] = {0, 0};
    int ns = 0;
    for (int i = 0; i < n_in && ns < 2; ++i)
        if (i != xi) { sv[ns] = (const float*)d_in[i]; ss[ns] = in_sizes[i]; ++ns; }
    if (ns < 2) return;
    const float* sz = sv[0];
    const float* th = sv[1];

    const long long big   = in_sizes[xi];
    const long long small = ss[0] < ss[1] ? ss[0] : ss[1];
    if (small <= 0 || big <= 0 || big % small) return;

    const long long T = big / small;                 // unit-invariant
    if (T <= 0 || T > (1 << 20)) return;

    const long long osz = out_size;
    long long D = 0;
    int interleaved = 0;
    if (osz % T == 0 && (osz / T == small || 4 * (osz / T) == small)) {
        D = osz / T;  interleaved = 0;               // f32 real [T,D]
    } else if (osz % (2 * T) == 0 &&
               (osz / (2 * T) == small || 4 * (osz / (2 * T)) == small)) {
        D = osz / (2 * T);  interleaved = 1;         // interleaved complex
    } else return;
    if (D <= 0 || D > (1 << 20)) return;

    const int C   = (int)((T + L_CHK - 1) / L_CHK);
    const int cpl = (C + 31) / 32;
    if ((long long)C * D > 2LL * SCRATCH_CAP_V4) return;   // float2 capacity

    dim3 blk(256);
    if (!interleaved && (D & 1) == 0 && cpl <= MAX_CPL) {
        const int P2 = (int)(D >> 1);
        dim3 g1((P2 + 255) / 256, (unsigned)C);
        dln_pass1_v2<<<g1, blk>>>(x, sz, th, (int)D, (int)T, C);
        dln_pass2_w<<<(unsigned)(((long long)D * 32 + 255) / 256), blk>>>(
            sz, th, (int)D, C, cpl);
        dln_pass3_real_v2<<<g1, blk>>>(x, sz, th, (float*)d_out,
                                       (int)D, (int)T, C, osz);
    } else {
        dim3 gA((unsigned)((D + 255) / 256), (unsigned)C);
        dln_pass1_s<<<gA, blk>>>(x, sz, th, (int)D, (int)T, C);
        if (cpl <= MAX_CPL)
            dln_pass2_w<<<(unsigned)(((long long)D * 32 + 255) / 256), blk>>>(
                sz, th, (int)D, C, cpl);
        else
            dln_pass2_s<<<(unsigned)((D + 255) / 256), blk>>>(sz, th, (int)D, C);
        if (interleaved)
            dln_pass3_cplx_s<<<gA, blk>>>(x, sz, th, (float*)d_out,
                                          (int)D, (int)T, C, osz);
        else
            dln_pass3_real_s<<<gA, blk>>>(x, sz, th, (float*)d_out,
                                          (int)D, (int)T, C, osz);
    }
}